// round 1
// baseline (speedup 1.0000x reference)
#include <cuda_runtime.h>

#define NNODE 50000
#define NEDGE 800000
#define TOTE  (NNODE + NEDGE)
#define NEG_SLOPE 0.2f
#define BN_EPS 1e-5f
#define INV_SQRT2 0.7071067811865476f

// ---------------- scratch (device globals: no allocations allowed) -------------
__device__ float g_h1  [NNODE * 128];
__device__ float g_out1[NNODE * 128];
__device__ float g_h2  [NNODE * 128];
__device__ float g_out2[NNODE * 128];
__device__ float g_res [NNODE * 128];
__device__ float g_z   [NNODE * 128];
__device__ float g_as1[NNODE * 4];
__device__ float g_ad1[NNODE * 4];
__device__ float g_m1 [NNODE * 4];
__device__ float g_den1[NNODE * 4];
__device__ float g_as2[NNODE];
__device__ float g_ad2[NNODE];
__device__ float g_m2 [NNODE];
__device__ float g_den2[NNODE];
__device__ float g_ee1[TOTE * 4];
__device__ float g_ee2[TOTE];
__device__ float g_stats[512];   // [sum1(128) | sq1(128) | sum2(128) | sq2(128)]

// ---------------- helpers ----------------
__device__ __forceinline__ void atomicMaxF(float* a, float v) {
    // IEEE ordered-int trick: int max for >=0, uint min for <0
    if (v >= 0.f) atomicMax((int*)a, __float_as_int(v));
    else          atomicMin((unsigned int*)a, __float_as_uint(v));
}

__device__ __forceinline__ void redAdd4(float* p, float a, float b, float c, float d) {
    asm volatile("red.global.add.v4.f32 [%0], {%1, %2, %3, %4};"
                 :: "l"(p), "f"(a), "f"(b), "f"(c), "f"(d) : "memory");
}

// ---------------- init: biases into outputs, -inf maxes, zero denoms/stats -----
__global__ void init_all(const float* __restrict__ bias1,
                         const float* __restrict__ bias2, int N) {
    int idx = blockIdx.x * blockDim.x + threadIdx.x;
    int tot = N * 128;
    if (idx < tot) {
        int c = idx & 127;
        g_out1[idx] = bias1[c];
        g_out2[idx] = bias2[c];
    }
    if (idx < N * 4) { g_m1[idx] = -1e30f; g_den1[idx] = 0.f; }
    if (idx < N)     { g_m2[idx] = -1e30f; g_den2[idx] = 0.f; }
    if (idx < 512)   g_stats[idx] = 0.f;
}

// ---------------- GEMM: C[N,128] = A[N,128] @ W[128,128] (+bias) ---------------
// block = 128 threads, 128 rows/block. W fully in SMEM (64KB), X tile 32x128.
// thread (w = warp, l = lane): 8 rows x 4 consecutive cols.
__global__ void gemm128(const float* __restrict__ A, const float* __restrict__ W,
                        const float* __restrict__ bias, float* __restrict__ C,
                        int nrows) {
    extern __shared__ float sm[];
    float* Ws = sm;            // 128*128
    float* Xs = sm + 16384;    // 32*128
    int tid = threadIdx.x;
    float4* Ws4 = (float4*)Ws;
    const float4* W4 = (const float4*)W;
    for (int i = tid; i < 4096; i += 128) Ws4[i] = W4[i];

    int w = tid >> 5, l = tid & 31;
    float4 bv = make_float4(0.f, 0.f, 0.f, 0.f);
    if (bias) bv = ((const float4*)bias)[l];
    int rb0 = blockIdx.x * 128;

    for (int t = 0; t < 4; t++) {
        int rbase = rb0 + t * 32;
        __syncthreads();
        float4* Xs4 = (float4*)Xs;
        for (int i = tid; i < 1024; i += 128) {
            int r = i >> 5, cc = i & 31;
            int row = rbase + r;
            Xs4[i] = (row < nrows) ? ((const float4*)(A + (long)row * 128))[cc]
                                   : make_float4(0.f, 0.f, 0.f, 0.f);
        }
        __syncthreads();

        float acc[8][4];
#pragma unroll
        for (int r = 0; r < 8; r++)
            acc[r][0] = acc[r][1] = acc[r][2] = acc[r][3] = 0.f;

        const float* xrow = Xs + (w * 8) * 128;
#pragma unroll 4
        for (int k = 0; k < 128; k++) {
            float4 wv = Ws4[k * 32 + l];
#pragma unroll
            for (int r = 0; r < 8; r++) {
                float xv = xrow[r * 128 + k];
                acc[r][0] = fmaf(xv, wv.x, acc[r][0]);
                acc[r][1] = fmaf(xv, wv.y, acc[r][1]);
                acc[r][2] = fmaf(xv, wv.z, acc[r][2]);
                acc[r][3] = fmaf(xv, wv.w, acc[r][3]);
            }
        }
#pragma unroll
        for (int r = 0; r < 8; r++) {
            int row = rbase + w * 8 + r;
            if (row < nrows) {
                float4 o = make_float4(acc[r][0] + bv.x, acc[r][1] + bv.y,
                                       acc[r][2] + bv.z, acc[r][3] + bv.w);
                ((float4*)(C + (long)row * 128))[l] = o;
            }
        }
    }
}

// ---------------- GEMM: C[N,32] = A[N,128] @ W[128,32] (+bias) -----------------
__global__ void gemm32(const float* __restrict__ A, const float* __restrict__ W,
                       const float* __restrict__ bias, float* __restrict__ C,
                       int nrows) {
    __shared__ float Ws[128 * 32];
    __shared__ float Xs[32 * 128];
    int tid = threadIdx.x;
    for (int i = tid; i < 4096; i += 128) Ws[i] = W[i];
    int w = tid >> 5, l = tid & 31;
    float bv = bias ? bias[l] : 0.f;
    int rb0 = blockIdx.x * 128;

    for (int t = 0; t < 4; t++) {
        int rbase = rb0 + t * 32;
        __syncthreads();
        float4* Xs4 = (float4*)Xs;
        for (int i = tid; i < 1024; i += 128) {
            int r = i >> 5, cc = i & 31;
            int row = rbase + r;
            Xs4[i] = (row < nrows) ? ((const float4*)(A + (long)row * 128))[cc]
                                   : make_float4(0.f, 0.f, 0.f, 0.f);
        }
        __syncthreads();
        float acc[8] = {};
#pragma unroll 4
        for (int k = 0; k < 128; k++) {
            float wv = Ws[k * 32 + l];
#pragma unroll
            for (int r = 0; r < 8; r++)
                acc[r] = fmaf(Xs[(w * 8 + r) * 128 + k], wv, acc[r]);
        }
#pragma unroll
        for (int r = 0; r < 8; r++) {
            int row = rbase + w * 8 + r;
            if (row < nrows) C[(long)row * 32 + l] = acc[r] + bv;
        }
    }
}

// ---------------- per-node attention logits --------------------------------
// conv1: 4 heads x 32 ch. One warp per node; 8 lanes per head.
__global__ void alpha1_k(const float* __restrict__ att_s,
                         const float* __restrict__ att_d, int N) {
    int gw = (blockIdx.x * blockDim.x + threadIdx.x) >> 5;
    int l = threadIdx.x & 31;
    if (gw >= N) return;
    int head = l >> 3, j = (l & 7) * 4;
    float4 hv = *(const float4*)(g_h1 + (long)gw * 128 + head * 32 + j);
    float4 as = *(const float4*)(att_s + head * 32 + j);
    float4 ad = *(const float4*)(att_d + head * 32 + j);
    float vs = hv.x * as.x + hv.y * as.y + hv.z * as.z + hv.w * as.w;
    float vd = hv.x * ad.x + hv.y * ad.y + hv.z * ad.z + hv.w * ad.w;
#pragma unroll
    for (int off = 4; off; off >>= 1) {
        vs += __shfl_down_sync(0xffffffffu, vs, off, 8);
        vd += __shfl_down_sync(0xffffffffu, vd, off, 8);
    }
    if ((l & 7) == 0) { g_as1[gw * 4 + head] = vs; g_ad1[gw * 4 + head] = vd; }
}

// conv2: 1 head x 128 ch. One warp per node, full-warp reduce.
__global__ void alpha2_k(const float* __restrict__ att_s,
                         const float* __restrict__ att_d, int N) {
    int gw = (blockIdx.x * blockDim.x + threadIdx.x) >> 5;
    int l = threadIdx.x & 31;
    if (gw >= N) return;
    float4 hv = *(const float4*)(g_h2 + (long)gw * 128 + l * 4);
    float4 as = ((const float4*)att_s)[l];
    float4 ad = ((const float4*)att_d)[l];
    float vs = hv.x * as.x + hv.y * as.y + hv.z * as.z + hv.w * as.w;
    float vd = hv.x * ad.x + hv.y * ad.y + hv.z * ad.z + hv.w * ad.w;
#pragma unroll
    for (int off = 16; off; off >>= 1) {
        vs += __shfl_down_sync(0xffffffffu, vs, off);
        vd += __shfl_down_sync(0xffffffffu, vd, off);
    }
    if (l == 0) { g_as2[gw] = vs; g_ad2[gw] = vd; }
}

// ---------------- edge passes (thread per edge) -----------------------------
__device__ __forceinline__ void edge_sd(const int* ei, int E, int e, int& s, int& d) {
    if (e < E) { s = ei[e]; d = ei[E + e]; }
    else       { s = d = e - E; }   // appended self-loop
}

__global__ void emax1(const int* __restrict__ ei, int E, int N) {
    int e = blockIdx.x * blockDim.x + threadIdx.x;
    if (e >= E + N) return;
    int s, d; edge_sd(ei, E, e, s, d);
    float4 as = *(const float4*)(g_as1 + s * 4);
    float4 ad = *(const float4*)(g_ad1 + d * 4);
    float v[4] = { as.x + ad.x, as.y + ad.y, as.z + ad.z, as.w + ad.w };
#pragma unroll
    for (int h = 0; h < 4; h++) {
        float vv = v[h] > 0.f ? v[h] : NEG_SLOPE * v[h];
        atomicMaxF(&g_m1[d * 4 + h], vv);
    }
}

__global__ void eexp1(const int* __restrict__ ei, int E, int N) {
    int e = blockIdx.x * blockDim.x + threadIdx.x;
    if (e >= E + N) return;
    int s, d; edge_sd(ei, E, e, s, d);
    float4 as = *(const float4*)(g_as1 + s * 4);
    float4 ad = *(const float4*)(g_ad1 + d * 4);
    float4 m  = *(const float4*)(g_m1  + d * 4);
    float v[4] = { as.x + ad.x, as.y + ad.y, as.z + ad.z, as.w + ad.w };
    float mm[4] = { m.x, m.y, m.z, m.w };
#pragma unroll
    for (int h = 0; h < 4; h++) {
        float vv = v[h] > 0.f ? v[h] : NEG_SLOPE * v[h];
        float ee = __expf(vv - mm[h]);
        g_ee1[e * 4 + h] = ee;
        atomicAdd(&g_den1[d * 4 + h], ee);
    }
}

__global__ void emax2(const int* __restrict__ ei, int E, int N) {
    int e = blockIdx.x * blockDim.x + threadIdx.x;
    if (e >= E + N) return;
    int s, d; edge_sd(ei, E, e, s, d);
    float v = g_as2[s] + g_ad2[d];
    v = v > 0.f ? v : NEG_SLOPE * v;
    atomicMaxF(&g_m2[d], v);
}

__global__ void eexp2(const int* __restrict__ ei, int E, int N) {
    int e = blockIdx.x * blockDim.x + threadIdx.x;
    if (e >= E + N) return;
    int s, d; edge_sd(ei, E, e, s, d);
    float v = g_as2[s] + g_ad2[d];
    v = v > 0.f ? v : NEG_SLOPE * v;
    float ee = __expf(v - g_m2[d]);
    g_ee2[e] = ee;
    atomicAdd(&g_den2[d], ee);
}

// ---------------- message scatter: warp per edge, red.v4 --------------------
__global__ void scatter1(const int* __restrict__ ei, int E, int N) {
    long gid = (long)blockIdx.x * blockDim.x + threadIdx.x;
    int e = (int)(gid >> 5), l = (int)(gid & 31);
    if (e >= E + N) return;
    int s, d; edge_sd(ei, E, e, s, d);
    int head = l >> 3;
    float a = g_ee1[e * 4 + head] *
              __fdividef(1.f, g_den1[d * 4 + head] + 1e-16f);
    float4 hv = *(const float4*)(g_h1 + (long)s * 128 + l * 4);
    redAdd4(g_out1 + (long)d * 128 + l * 4, hv.x * a, hv.y * a, hv.z * a, hv.w * a);
}

__global__ void scatter2(const int* __restrict__ ei, int E, int N) {
    long gid = (long)blockIdx.x * blockDim.x + threadIdx.x;
    int e = (int)(gid >> 5), l = (int)(gid & 31);
    if (e >= E + N) return;
    int s, d; edge_sd(ei, E, e, s, d);
    float a = g_ee2[e] * __fdividef(1.f, g_den2[d] + 1e-16f);
    float4 hv = *(const float4*)(g_h2 + (long)s * 128 + l * 4);
    redAdd4(g_out2 + (long)d * 128 + l * 4, hv.x * a, hv.y * a, hv.z * a, hv.w * a);
}

// ---------------- batch norm -------------------------------------------------
__global__ void bn_reduce(const float* __restrict__ X, float* __restrict__ sum,
                          float* __restrict__ sq, int N) {
    int c = threadIdx.x;           // 128 channels
    int r0 = blockIdx.x * 512;
    int r1 = min(r0 + 512, N);
    float s = 0.f, q = 0.f;
    for (int r = r0; r < r1; r++) {
        float v = X[(long)r * 128 + c];
        s += v; q += v * v;
    }
    atomicAdd(&sum[c], s);
    atomicAdd(&sq[c], q);
}

__global__ void bn_apply_relu(float* __restrict__ X, const float* __restrict__ sum,
                              const float* __restrict__ sq,
                              const float* __restrict__ gamma,
                              const float* __restrict__ beta, int N) {
    long idx = (long)blockIdx.x * blockDim.x + threadIdx.x;
    if (idx >= (long)N * 128) return;
    int c = (int)(idx & 127);
    float invN = 1.f / (float)N;
    float mu = sum[c] * invN;
    float var = sq[c] * invN - mu * mu;
    float sc = gamma[c] * rsqrtf(var + BN_EPS);
    float v = (X[idx] - mu) * sc + beta[c];
    X[idx] = v > 0.f ? v : 0.f;
}

// bn2 + relu + residual-add + *1/sqrt(2) fused; writes g_z
__global__ void bn_apply_relu_res(const float* __restrict__ sum,
                                  const float* __restrict__ sq,
                                  const float* __restrict__ gamma,
                                  const float* __restrict__ beta, int N) {
    long idx = (long)blockIdx.x * blockDim.x + threadIdx.x;
    if (idx >= (long)N * 128) return;
    int c = (int)(idx & 127);
    float invN = 1.f / (float)N;
    float mu = sum[c] * invN;
    float var = sq[c] * invN - mu * mu;
    float sc = gamma[c] * rsqrtf(var + BN_EPS);
    float v = (g_out2[idx] - mu) * sc + beta[c];
    v = v > 0.f ? v : 0.f;
    g_z[idx] = (v + g_res[idx]) * INV_SQRT2;
}

// ---------------- launch ------------------------------------------------------
extern "C" void kernel_launch(void* const* d_in, const int* in_sizes, int n_in,
                              void* d_out, int out_size) {
    const float* x        = (const float*)d_in[0];
    const int*   ei       = (const int*)  d_in[1];
    const float* W1       = (const float*)d_in[2];
    const float* att_src1 = (const float*)d_in[3];
    const float* att_dst1 = (const float*)d_in[4];
    const float* bias1    = (const float*)d_in[5];
    const float* W2       = (const float*)d_in[6];
    const float* att_src2 = (const float*)d_in[7];
    const float* att_dst2 = (const float*)d_in[8];
    const float* bias2    = (const float*)d_in[9];
    const float* gamma1   = (const float*)d_in[10];
    const float* beta1    = (const float*)d_in[11];
    const float* gamma2   = (const float*)d_in[12];
    const float* beta2    = (const float*)d_in[13];
    const float* W_res    = (const float*)d_in[14];
    const float* b_res    = (const float*)d_in[15];
    const float* W_fin    = (const float*)d_in[16];
    const float* b_fin    = (const float*)d_in[17];
    float* out = (float*)d_out;

    int N = in_sizes[0] / 128;
    int E = in_sizes[1] / 2;
    int tot = E + N;

    float *p_h1, *p_out1, *p_h2, *p_out2, *p_res, *p_z, *p_stats;
    cudaGetSymbolAddress((void**)&p_h1,   g_h1);
    cudaGetSymbolAddress((void**)&p_out1, g_out1);
    cudaGetSymbolAddress((void**)&p_h2,   g_h2);
    cudaGetSymbolAddress((void**)&p_out2, g_out2);
    cudaGetSymbolAddress((void**)&p_res,  g_res);
    cudaGetSymbolAddress((void**)&p_z,    g_z);
    cudaGetSymbolAddress((void**)&p_stats, g_stats);

    const int GEMM_SMEM = (16384 + 4096) * 4;  // 80KB
    cudaFuncSetAttribute(gemm128, cudaFuncAttributeMaxDynamicSharedMemorySize, GEMM_SMEM);

    int ew = (tot + 255) / 256;                   // thread-per-edge grids
    int sw = (int)(((long)tot * 32 + 255) / 256); // warp-per-edge grids
    int nb128 = (N * 128 + 255) / 256;            // element-wise over N*128
    int gb = (N + 127) / 128;                     // gemm row blocks
    int wb = (N * 32 + 255) / 256;                // warp-per-node grids

    init_all<<<nb128, 256>>>(bias1, bias2, N);

    // conv1
    gemm128<<<gb, 128, GEMM_SMEM>>>(x, W1, nullptr, p_h1, N);
    gemm128<<<gb, 128, GEMM_SMEM>>>(x, W_res, b_res, p_res, N);  // residual branch
    alpha1_k<<<wb, 256>>>(att_src1, att_dst1, N);
    emax1<<<ew, 256>>>(ei, E, N);
    eexp1<<<ew, 256>>>(ei, E, N);
    scatter1<<<sw, 256>>>(ei, E, N);
    bn_reduce<<<(N + 511) / 512, 128>>>(p_out1, p_stats, p_stats + 128, N);
    bn_apply_relu<<<nb128, 256>>>(p_out1, p_stats, p_stats + 128, gamma1, beta1, N);

    // conv2
    gemm128<<<gb, 128, GEMM_SMEM>>>(p_out1, W2, nullptr, p_h2, N);
    alpha2_k<<<wb, 256>>>(att_src2, att_dst2, N);
    emax2<<<ew, 256>>>(ei, E, N);
    eexp2<<<ew, 256>>>(ei, E, N);
    scatter2<<<sw, 256>>>(ei, E, N);
    bn_reduce<<<(N + 511) / 512, 128>>>(p_out2, p_stats + 256, p_stats + 384, N);
    bn_apply_relu_res<<<nb128, 256>>>(p_stats + 256, p_stats + 384, gamma2, beta2, N);

    // final projection
    gemm32<<<gb, 128>>>(p_z, W_fin, b_fin, out, N);
}